// round 4
// baseline (speedup 1.0000x reference)
#include <cuda_runtime.h>
#include <cstdint>

// KV-cache scatter-copy, pure HBM streaming.
//   L=8, B=2, H=8, S_FULL=4096, S_NEW=4, D=128, fp32
// out (2,L,B,H,S_FULL,D) = stack(past_k, past_v) with a 4-row window per
// (l,b,h) overwritten from new_k/new_v at target_positions[b].
//
// R4: Blackwell 256-bit vector ld/st (v8.f32). 4x float8 per thread,
// front-batched loads, streaming (.cs) both directions, block-uniform
// kv/l/b/h decode.

static constexpr unsigned D8       = 16;                       // float8 per row (D=128)
static constexpr unsigned S_FULL   = 4096;
static constexpr unsigned S_NEW    = 4;
static constexpr unsigned H        = 8;
static constexpr unsigned B        = 2;
static constexpr unsigned L        = 8;
static constexpr unsigned PAST_F8  = L * B * H * S_FULL * D8;  // 2^23
static constexpr unsigned TOTAL_F8 = 2u * PAST_F8;             // 2^24

static constexpr unsigned TPB  = 256;
static constexpr unsigned U    = 4;                            // 4 x 32B = 128B/thread
static constexpr unsigned TILE = TPB * U;                      // 1024 float8 per block

// 256-bit streaming global load: 8 consecutive f32 from a 32B-aligned address.
__device__ __forceinline__ void ldcs_v8(const float* __restrict__ p, float* r) {
    asm volatile(
        "ld.global.cs.v8.f32 {%0,%1,%2,%3,%4,%5,%6,%7}, [%8];"
        : "=f"(r[0]), "=f"(r[1]), "=f"(r[2]), "=f"(r[3]),
          "=f"(r[4]), "=f"(r[5]), "=f"(r[6]), "=f"(r[7])
        : "l"(p));
}

// 256-bit streaming global store.
__device__ __forceinline__ void stcs_v8(float* p, const float* r) {
    asm volatile(
        "st.global.cs.v8.f32 [%0], {%1,%2,%3,%4,%5,%6,%7,%8};"
        :: "l"(p),
           "f"(r[0]), "f"(r[1]), "f"(r[2]), "f"(r[3]),
           "f"(r[4]), "f"(r[5]), "f"(r[6]), "f"(r[7])
        : "memory");
}

__global__ void __launch_bounds__(TPB) kv_scatter_copy_v8(
    const float* __restrict__ pk,
    const float* __restrict__ pv,
    const float* __restrict__ nk,
    const float* __restrict__ nv,
    const int*   __restrict__ tpos,
    float*       __restrict__ out)
{
    const unsigned base = blockIdx.x * TILE + threadIdx.x;      // in float8 units

    // Bits >= 16 (h|b|l|kv) are uniform across the block (TILE = 2^10).
    const unsigned r  = base >> 16;
    const unsigned h  = r & (H - 1);
    const unsigned b  = (r >> 3) & (B - 1);
    const unsigned l  = (r >> 4) & (L - 1);
    const unsigned kv = r >> 7;

    const unsigned off = (unsigned)__ldg(&tpos[b]);

    const float* __restrict__ past = kv ? pv : pk;      // same layout as out slab
    const float* __restrict__ nw   = (kv ? nv : nk)
                                     + (size_t)(((l * B + b) * H + h) * S_NEW) * (D8 * 8);

    float v[U][8];
#pragma unroll
    for (unsigned u = 0; u < U; u++) {
        const unsigned i  = base + u * TPB;             // float8 index
        const unsigned s  = (i >> 4) & (S_FULL - 1);
        const unsigned d8 = i & (D8 - 1);
        const unsigned w  = s - off;                    // in-window iff < S_NEW (unsigned wrap)
        const float* p = (w < S_NEW)
                       ? (nw + ((size_t)(w * D8 + d8) << 3))
                       : (past + ((size_t)(i & (PAST_F8 - 1)) << 3));
        ldcs_v8(p, v[u]);
    }
#pragma unroll
    for (unsigned u = 0; u < U; u++) {
        stcs_v8(out + ((size_t)(base + u * TPB) << 3), v[u]);
    }
}

extern "C" void kernel_launch(void* const* d_in, const int* in_sizes, int n_in,
                              void* d_out, int out_size)
{
    const float* pk = (const float*)d_in[0];
    const float* pv = (const float*)d_in[1];
    const float* nk = (const float*)d_in[2];
    const float* nv = (const float*)d_in[3];
    const int*   tp = (const int*)d_in[4];
    float*       out = (float*)d_out;

    constexpr unsigned blocks = TOTAL_F8 / TILE;        // 16384
    kv_scatter_copy_v8<<<blocks, TPB>>>(pk, pv, nk, nv, tp, out);
}